// round 14
// baseline (speedup 1.0000x reference)
#include <cuda_runtime.h>
#include <cuda_bf16.h>

// ---------------- problem constants ----------------
#define NB    64          // batch
#define IMG   128         // input H=W
#define C1    64          // encoder mid channels
#define H1    64          // after stride-2 conv1
#define DQ    256         // code dim
#define H3    32          // latent H=W
#define KC    1024        // codebook size
#define NROWS (NB*H3*H3)  // 65536 latent vectors

// ---------------- scratch (device globals; no allocs allowed) ----------------
__device__ float g_z1[NB*C1*H1*H1];        // conv1 out, NCHW
__device__ float g_z2[NB*C1*H1*H1];        // conv2 out, NCHW
__device__ float g_z3[NROWS*DQ];           // conv3 out (z), NHWC rows
__device__ float g_e [NROWS*DQ];           // quantized e, NHWC rows
__device__ float g_d1[NB*64*64*64];        // deconv1 out, NHWC
__device__ float g_d2[NB*128*128*64];      // deconv2 out, NHWC
__device__ int   g_idx[NROWS];
__device__ float g_wnorm[KC];
__device__ float g_part[256];

// ---------------- packed f32x2 helpers ----------------
typedef unsigned long long ull;
__device__ __forceinline__ void ffma2(ull& acc, ull a, ull b) {
    asm("fma.rn.f32x2 %0, %1, %2, %0;" : "+l"(acc) : "l"(a), "l"(b));
}
__device__ __forceinline__ ull pk2(float lo, float hi) {
    ull r; asm("mov.b64 %0, {%1, %2};" : "=l"(r) : "f"(lo), "f"(hi)); return r;
}
__device__ __forceinline__ float lo32(ull v) { return __uint_as_float((unsigned)(v & 0xFFFFFFFFull)); }
__device__ __forceinline__ float hi32(ull v) { return __uint_as_float((unsigned)(v >> 32)); }

// ================= conv1: 1->64, 5x5, s2, p2, ReLU =================
__global__ __launch_bounds__(256) void k_conv1(const float* __restrict__ x,
                                               const float* __restrict__ w,
                                               const float* __restrict__ bias) {
    __shared__ float s_in[35*35];
    __shared__ float s_w[64*25];
    const int b = blockIdx.z;
    const int X0 = blockIdx.x*16, Y0 = blockIdx.y*16;
    const int tid = threadIdx.y*16 + threadIdx.x;
    for (int i = tid; i < 1600; i += 256) s_w[i] = w[i];
    const int iy0 = 2*Y0 - 2, ix0 = 2*X0 - 2;
    const float* xb = x + b*IMG*IMG;
    for (int i = tid; i < 35*35; i += 256) {
        int r = i/35, c = i%35;
        int iy = iy0 + r, ix = ix0 + c;
        float v = 0.f;
        if (iy >= 0 && iy < IMG && ix >= 0 && ix < IMG) v = xb[iy*IMG + ix];
        s_in[i] = v;
    }
    __syncthreads();
    const int ty = threadIdx.y, tx = threadIdx.x;
    float in_reg[25];
#pragma unroll
    for (int ky = 0; ky < 5; ky++)
#pragma unroll
        for (int kx = 0; kx < 5; kx++)
            in_reg[ky*5+kx] = s_in[(2*ty+ky)*35 + 2*tx + kx];
    const int oy = Y0 + ty, ox = X0 + tx;
    float* outp = g_z1 + ((size_t)b*64*64*64) + oy*64 + ox;
#pragma unroll 4
    for (int oc = 0; oc < 64; oc++) {
        float s = bias[oc];
#pragma unroll
        for (int k = 0; k < 25; k++) s = fmaf(s_w[oc*25+k], in_reg[k], s);
        outp[(size_t)oc*4096] = fmaxf(s, 0.f);
    }
}

// ================= conv2 (f32x2): 64->64, 5x5, s1, p2, ReLU =================
__global__ __launch_bounds__(256) void k_conv2(const float* __restrict__ w,
                                               const float* __restrict__ bias) {
    __shared__ float2 s_in2[12*21];
    __shared__ float  s_w[64*25];
    const int b = blockIdx.z;
    const int X0 = blockIdx.x*32, Y0 = blockIdx.y*8;
    const int tid = threadIdx.x;
    const int ocg  = tid >> 5;
    const int slot = tid & 31;
    const int sy = slot >> 2, sx = slot & 3;

    ull acc[8][4];
#pragma unroll
    for (int j = 0; j < 8; j++)
#pragma unroll
        for (int kp = 0; kp < 4; kp++) acc[j][kp] = 0ull;

    for (int ic = 0; ic < 64; ic++) {
        const float* inp = g_z1 + ((size_t)(b*64 + ic))*4096;
        for (int i = tid; i < 240; i += 256) {
            int r = i/20, c = i%20;
            int iy = Y0 - 2 + r;
            int ix0 = X0 - 2 + c, ix1 = ix0 + 16;
            float v0 = 0.f, v1 = 0.f;
            if (iy >= 0 && iy < 64) {
                if (ix0 >= 0 && ix0 < 64) v0 = inp[iy*64 + ix0];
                if (ix1 >= 0 && ix1 < 64) v1 = inp[iy*64 + ix1];
            }
            s_in2[r*21 + c] = make_float2(v0, v1);
        }
        for (int i = tid; i < 1600; i += 256)
            s_w[i] = w[((i/25)*64 + ic)*25 + (i%25)];
        __syncthreads();

#pragma unroll
        for (int ky = 0; ky < 5; ky++) {
#pragma unroll
            for (int kx = 0; kx < 5; kx++) {
                const int tap = ky*5 + kx;
                ull wd[8];
#pragma unroll
                for (int j = 0; j < 8; j++) {
                    float wv = s_w[(ocg*8 + j)*25 + tap];
                    wd[j] = pk2(wv, wv);
                }
                ull ip[4];
#pragma unroll
                for (int kp = 0; kp < 4; kp++)
                    ip[kp] = *reinterpret_cast<const ull*>(&s_in2[(sy+ky)*21 + sx + 4*kp + kx]);
#pragma unroll
                for (int j = 0; j < 8; j++)
#pragma unroll
                    for (int kp = 0; kp < 4; kp++)
                        ffma2(acc[j][kp], ip[kp], wd[j]);
            }
        }
        __syncthreads();
    }
    const int oy = Y0 + sy;
#pragma unroll
    for (int j = 0; j < 8; j++) {
        const int oc = ocg*8 + j;
        const float bb = bias[oc];
        float* o = g_z2 + ((size_t)(b*64 + oc))*4096 + oy*64;
#pragma unroll
        for (int kp = 0; kp < 4; kp++) {
            int x0 = X0 + sx + 4*kp;
            o[x0]      = fmaxf(lo32(acc[j][kp]) + bb, 0.f);
            o[x0 + 16] = fmaxf(hi32(acc[j][kp]) + bb, 0.f);
        }
    }
}

// ================= conv3 (f32x2): 64->256, 5x5, s2, p2 (linear) -> NHWC z =================
__global__ __launch_bounds__(256) void k_conv3(const float* __restrict__ w,
                                               const float* __restrict__ bias) {
    __shared__ float2 s_in2[19*35];
    __shared__ float  s_w[64*25];
    const int bz = blockIdx.z;
    const int b = bz >> 2, ocb = bz & 3;
    const int Y0 = blockIdx.y*8;
    const int tid = threadIdx.x;
    const int ocg  = tid >> 5;
    const int slot = tid & 31;
    const int sy = slot >> 2, sx = slot & 3;

    ull acc[8][4];
#pragma unroll
    for (int j = 0; j < 8; j++)
#pragma unroll
        for (int kp = 0; kp < 4; kp++) acc[j][kp] = 0ull;

    const int iy0 = 2*Y0 - 2;
    for (int ic = 0; ic < 64; ic++) {
        const float* inp = g_z2 + ((size_t)(b*64 + ic))*4096;
        for (int i = tid; i < 665; i += 256) {
            int r = i/35, c = i%35;
            int iy = iy0 + r;
            int ix0 = c - 2, ix1 = c + 30;
            float v0 = 0.f, v1 = 0.f;
            if (iy >= 0 && iy < 64) {
                if (ix0 >= 0 && ix0 < 64) v0 = inp[iy*64 + ix0];
                if (ix1 < 64)             v1 = inp[iy*64 + ix1];
            }
            s_in2[r*35 + c] = make_float2(v0, v1);
        }
        for (int i = tid; i < 1600; i += 256) {
            int ocl = i/25, tap = i%25;
            s_w[i] = w[(((ocb*64 + ocl))*64 + ic)*25 + tap];
        }
        __syncthreads();

#pragma unroll
        for (int ky = 0; ky < 5; ky++) {
#pragma unroll
            for (int kx = 0; kx < 5; kx++) {
                const int tap = ky*5 + kx;
                ull wd[8];
#pragma unroll
                for (int j = 0; j < 8; j++) {
                    float wv = s_w[(ocg*8 + j)*25 + tap];
                    wd[j] = pk2(wv, wv);
                }
                ull ip[4];
#pragma unroll
                for (int kp = 0; kp < 4; kp++)
                    ip[kp] = *reinterpret_cast<const ull*>(&s_in2[(2*sy+ky)*35 + 2*sx + 8*kp + kx]);
#pragma unroll
                for (int j = 0; j < 8; j++)
#pragma unroll
                    for (int kp = 0; kp < 4; kp++)
                        ffma2(acc[j][kp], ip[kp], wd[j]);
            }
        }
        __syncthreads();
    }
    const int oy = Y0 + sy;
#pragma unroll
    for (int j = 0; j < 8; j++) {
        const int oc = ocb*64 + ocg*8 + j;
        const float bb = bias[oc];
#pragma unroll
        for (int kp = 0; kp < 4; kp++) {
            int x0 = sx + 4*kp;
            size_t base = ((size_t)(b*H3 + oy)*H3)*DQ;
            g_z3[base + (size_t)x0*DQ + oc]        = lo32(acc[j][kp]) + bb;
            g_z3[base + (size_t)(x0+16)*DQ + oc]   = hi32(acc[j][kp]) + bb;
        }
    }
}

// ================= codebook norms =================
__global__ void k_wnorm(const float* __restrict__ cb) {
    int wid = (blockIdx.x*blockDim.x + threadIdx.x) >> 5;
    int lane = threadIdx.x & 31;
    if (wid >= KC) return;
    float s = 0.f;
    for (int d = lane; d < DQ; d += 32) { float v = cb[wid*DQ + d]; s = fmaf(v, v, s); }
#pragma unroll
    for (int off = 16; off > 0; off >>= 1) s += __shfl_xor_sync(0xFFFFFFFFu, s, off);
    if (lane == 0) g_wnorm[wid] = s;
}

// ================= quantize (f32x2, R12 version): argmin over 1024 codes =================
__device__ __forceinline__ unsigned fkey(float f) {
    unsigned u = __float_as_uint(f);
    return (u & 0x80000000u) ? ~u : (u | 0x80000000u);
}
__global__ __launch_bounds__(256) void k_quant(const float* __restrict__ cb) {
    __shared__ float sA [64*65];       // [row][d]
    __shared__ float sBt[64*66];       // [d][code]  (transposed tile)
    __shared__ float s_wn[64];
    __shared__ unsigned long long s_best[64];
    const int tid = threadIdx.x;
    const int row0 = blockIdx.x*64;
    if (tid < 64) s_best[tid] = 0xFFFFFFFFFFFFFFFFULL;
    const int cg = tid & 15, rg = tid >> 4;

    for (int cc = 0; cc < 16; cc++) {
        __syncthreads();
        if (tid < 64) s_wn[tid] = g_wnorm[cc*64 + tid];
        ull acc2[4][2];
#pragma unroll
        for (int i = 0; i < 4; i++) { acc2[i][0] = 0ull; acc2[i][1] = 0ull; }

        for (int dc = 0; dc < 4; dc++) {
            for (int i = tid; i < 4096; i += 256) {
                int r = i >> 6, d = i & 63;
                sA[r*65 + d] = g_z3[(size_t)(row0 + r)*DQ + dc*64 + d];
            }
            for (int i = tid; i < 4096; i += 256) {
                int c = i >> 6, d = i & 63;
                sBt[d*66 + c] = cb[(size_t)(cc*64 + c)*DQ + dc*64 + d];
            }
            __syncthreads();
#pragma unroll 4
            for (int d = 0; d < 64; d++) {
                ull a2[4];
#pragma unroll
                for (int i = 0; i < 4; i++) {
                    float av = sA[(rg*4 + i)*65 + d];
                    a2[i] = pk2(av, av);
                }
                ull b0 = *reinterpret_cast<const ull*>(&sBt[d*66 + cg*4]);
                ull b1 = *reinterpret_cast<const ull*>(&sBt[d*66 + cg*4 + 2]);
#pragma unroll
                for (int i = 0; i < 4; i++) {
                    ffma2(acc2[i][0], a2[i], b0);
                    ffma2(acc2[i][1], a2[i], b1);
                }
            }
            __syncthreads();
        }
#pragma unroll
        for (int i = 0; i < 4; i++) {
            int r = rg*4 + i;
            float dot[4] = { lo32(acc2[i][0]), hi32(acc2[i][0]),
                             lo32(acc2[i][1]), hi32(acc2[i][1]) };
            unsigned long long best = 0xFFFFFFFFFFFFFFFFULL;
#pragma unroll
            for (int j = 0; j < 4; j++) {
                int c = cc*64 + cg*4 + j;
                float dist = s_wn[cg*4 + j] - 2.f*dot[j];
                unsigned long long p = ((unsigned long long)fkey(dist) << 32) | (unsigned)c;
                if (p < best) best = p;
            }
            atomicMin(&s_best[r], best);
        }
    }
    __syncthreads();
    if (tid < 64) g_idx[row0 + tid] = (int)(s_best[tid] & 0xFFFFFFFFULL);
}

// ================= gather e + partial diff sums =================
__global__ __launch_bounds__(256) void k_gather(const float* __restrict__ cb) {
    const int tid = threadIdx.x;
    float local = 0.f;
    for (int it = 0; it < 256; it++) {
        int row = it*256 + blockIdx.x;
        int id = g_idx[row];
        float ev = cb[(size_t)id*DQ + tid];
        float zv = g_z3[(size_t)row*DQ + tid];
        g_e[(size_t)row*DQ + tid] = ev;
        float d = zv - ev;
        local = fmaf(d, d, local);
    }
    __shared__ float red[256];
    red[tid] = local;
    __syncthreads();
    for (int s = 128; s > 0; s >>= 1) {
        if (tid < s) red[tid] += red[tid + s];
        __syncthreads();
    }
    if (tid == 0) g_part[blockIdx.x] = red[0];
}

__global__ void k_diff_final(float* __restrict__ out) {
    __shared__ float red[256];
    int tid = threadIdx.x;
    red[tid] = g_part[tid];
    __syncthreads();
    for (int s = 128; s > 0; s >>= 1) {
        if (tid < s) red[tid] += red[tid + s];
        __syncthreads();
    }
    if (tid == 0) out[0] = red[0] * (1.0f / 16777216.0f);
}

// ================= deconv (f32x2, double-buffered, pre-packed inputs) + ReLU =================
// ONLY change vs R12: inputs staged PRE-PACKED as (v,v) float2 -> hot loop
// LDS.64s directly into rp, deleting 12 pk2/icl. FMA order unchanged -> bit-exact.
template<int STAGE>
__global__ __launch_bounds__(256) void k_deconv(const float* __restrict__ w,
                                                const float* __restrict__ bias) {
    constexpr int ICTOT = (STAGE == 1) ? 256 : 64;
    constexpr int INHW  = (STAGE == 1) ? 32  : 64;
    constexpr int OUTHW = (STAGE == 1) ? 64  : 128;
    constexpr int NICC  = ICTOT / 8;
    const float* __restrict__ in  = (STAGE == 1) ? g_e  : g_d1;
    float*       __restrict__ out = (STAGE == 1) ? g_d1 : g_d2;

    __shared__ float2 s_in2[2][900];                  // 10x10 px x 8 ic, pitch 9, (v,v)
    __shared__ __align__(16) float s_w[2][8*16*34];   // [icl][tap][oc32] pitch 34
    const int b = blockIdx.z >> 1, ochalf = blockIdx.z & 1;
    const int X0 = blockIdx.x*16, Y0 = blockIdx.y*16;
    const int tid = threadIdx.x;
    const int ocgrp = tid >> 5;        // 0..7 -> 4 oc each
    const int slot = tid & 31;
    const int sy = slot >> 2, sx = slot & 3;
    ull acc2[2][4][2];                 // [dy][dx][oc-pair]
#pragma unroll
    for (int a = 0; a < 2; a++)
#pragma unroll
        for (int c = 0; c < 4; c++)
#pragma unroll
            for (int o = 0; o < 2; o++) acc2[a][c][o] = 0ull;

    const int iyb = (Y0 >> 1) - 1, ixb = (X0 >> 1) - 1;

    auto stage = [&](int icc, int buf) {
        for (int i = tid; i < 800; i += 256) {
            int icl = i & 7;
            int p = i >> 3;
            int c = p % 10, r = p / 10;
            int iy = iyb + r, ix = ixb + c;
            float v = 0.f;
            if (iy >= 0 && iy < INHW && ix >= 0 && ix < INHW)
                v = in[((size_t)(b*INHW + iy)*INHW + ix)*ICTOT + icc*8 + icl];
            s_in2[buf][p*9 + icl] = make_float2(v, v);
        }
        // COALESCED weight staging: linear gmem j -> smem scatter.
        for (int j = tid; j < 4096; j += 256) {
            int icl = j >> 9, rem = j & 511;
            int ocl = rem >> 4, tap = rem & 15;
            s_w[buf][(icl*16 + tap)*34 + ocl] =
                w[(size_t)icc*8192 + icl*1024 + ochalf*512 + rem];
        }
    };

    stage(0, 0);
    __syncthreads();

    for (int icc = 0; icc < NICC; icc++) {
        const int cur = icc & 1;
        if (icc + 1 < NICC) stage(icc + 1, cur ^ 1);

#pragma unroll
        for (int icl = 0; icl < 8; icl++) {
            ull rp[3][4];
#pragma unroll
            for (int a = 0; a < 3; a++)
#pragma unroll
                for (int c = 0; c < 4; c++)
                    rp[a][c] = *reinterpret_cast<const ull*>(
                        &s_in2[cur][((sy + a)*10 + 2*sx + c)*9 + icl]);
#pragma unroll
            for (int op = 0; op < 2; op++) {
                const int wofs = ocgrp*4 + op*2;
#pragma unroll
                for (int dy = 0; dy < 2; dy++) {
                    // 8 taps live for this dy: ky = (1-dy)+2a, kx = 0..3
                    ull w2[8];
#pragma unroll
                    for (int a = 0; a < 2; a++)
#pragma unroll
                        for (int kx = 0; kx < 4; kx++)
                            w2[a*4 + kx] = *reinterpret_cast<const ull*>(
                                &s_w[cur][(icl*16 + ((1 - dy) + 2*a)*4 + kx)*34 + wofs]);
#pragma unroll
                    for (int dx = 0; dx < 4; dx++) {
                        const int ib = 1 + ((dx + 1) >> 1);
#pragma unroll
                        for (int a = 0; a < 2; a++)
#pragma unroll
                            for (int c = 0; c < 2; c++) {
                                int kx = ((dx & 1) ? 0 : 1) + 2*c;
                                ffma2(acc2[dy][dx][op], rp[dy + 1 - a][ib - c], w2[a*4 + kx]);
                            }
                    }
                }
            }
        }
        __syncthreads();
    }
#pragma unroll
    for (int dy = 0; dy < 2; dy++)
#pragma unroll
        for (int dx = 0; dx < 4; dx++) {
            int py = Y0 + 2*sy + dy;
            int px = X0 + 4*sx + dx;
            float* o = out + ((size_t)(b*OUTHW + py)*OUTHW + px)*64 + ochalf*32;
#pragma unroll
            for (int op = 0; op < 2; op++) {
                int ocl = ocgrp*4 + op*2;
                int oc  = ochalf*32 + ocl;
                o[ocl]     = fmaxf(lo32(acc2[dy][dx][op]) + bias[oc],     0.f);
                o[ocl + 1] = fmaxf(hi32(acc2[dy][dx][op]) + bias[oc + 1], 0.f);
            }
        }
}

// ================= final conv 64->1, 3x3, s1, p1 + tanh =================
__global__ __launch_bounds__(256) void k_final(const float* __restrict__ w,
                                               const float* __restrict__ bias,
                                               float* __restrict__ out) {
    __shared__ float s_w[576];
    __shared__ float s_in[324*17 + 16];
    const int b = blockIdx.z;
    const int X0 = blockIdx.x*16, Y0 = blockIdx.y*16;
    const int tid = threadIdx.x;
    const int ty = tid >> 4, tx = tid & 15;
    for (int i = tid; i < 576; i += 256) s_w[i] = w[i];
    float acc = bias[0];
    for (int icc = 0; icc < 4; icc++) {
        __syncthreads();
        for (int i = tid; i < 324*16; i += 256) {
            int icl = i & 15;
            int p = i >> 4;
            int c = p % 18, r = p / 18;
            int iy = Y0 - 1 + r, ix = X0 - 1 + c;
            float v = 0.f;
            if (iy >= 0 && iy < 128 && ix >= 0 && ix < 128)
                v = g_d2[((size_t)(b*128 + iy)*128 + ix)*64 + icc*16 + icl];
            s_in[p*17 + icl] = v;
        }
        __syncthreads();
#pragma unroll 4
        for (int icl = 0; icl < 16; icl++) {
            int ic = icc*16 + icl;
#pragma unroll
            for (int ky = 0; ky < 3; ky++)
#pragma unroll
                for (int kx = 0; kx < 3; kx++)
                    acc = fmaf(s_w[ic*9 + ky*3 + kx],
                               s_in[((ty + ky)*18 + tx + kx)*17 + icl], acc);
        }
    }
    out[(size_t)b*16384 + (Y0 + ty)*128 + (X0 + tx)] = tanhf(acc);
}

// ================= launch =================
extern "C" void kernel_launch(void* const* d_in, const int* in_sizes, int n_in,
                              void* d_out, int out_size) {
    const float* ptr[14];
    {
        bool used[32];
        for (int i = 0; i < 32; i++) used[i] = false;
        auto find_nth = [&](int sz) -> const float* {
            for (int i = 0; i < n_in; i++) {
                if (!used[i] && in_sizes[i] == sz) { used[i] = true; return (const float*)d_in[i]; }
            }
            return (const float*)d_in[0];
        };
        ptr[0]  = find_nth(1048576);  // x
        ptr[1]  = find_nth(1600);     // enc_w1
        ptr[3]  = find_nth(102400);   // enc_w2
        ptr[5]  = find_nth(409600);   // enc_w3
        ptr[6]  = find_nth(256);      // enc_b3
        ptr[7]  = find_nth(262144);   // codebook (first occurrence)
        ptr[8]  = find_nth(262144);   // dec_w1  (second occurrence)
        ptr[10] = find_nth(65536);    // dec_w2
        ptr[12] = find_nth(576);      // dec_w3
        ptr[13] = find_nth(1);        // dec_b3
        ptr[2]  = find_nth(64);       // enc_b1 (all 64-vecs are zeros)
        ptr[4]  = find_nth(64);       // enc_b2
        ptr[9]  = find_nth(64);       // dec_b1
        ptr[11] = find_nth(64);       // dec_b2
    }
    float* out = (float*)d_out;

    k_conv1<<<dim3(4,4,NB), dim3(16,16)>>>(ptr[0], ptr[1], ptr[2]);
    k_conv2<<<dim3(2,8,NB), 256>>>(ptr[3], ptr[4]);
    k_conv3<<<dim3(1,4,NB*4), 256>>>(ptr[5], ptr[6]);
    k_wnorm<<<128, 256>>>(ptr[7]);
    k_quant<<<NROWS/64, 256>>>(ptr[7]);
    k_gather<<<256, 256>>>(ptr[7]);
    k_diff_final<<<1, 256>>>(out + (out_size - 1));
    k_deconv<1><<<dim3(4,4,NB*2), 256>>>(ptr[8], ptr[9]);
    k_deconv<2><<<dim3(8,8,NB*2), 256>>>(ptr[10], ptr[11]);
    k_final<<<dim3(8,8,NB), 256>>>(ptr[12], ptr[13], out);
}

// round 15
// speedup vs baseline: 1.1373x; 1.1373x over previous
#include <cuda_runtime.h>
#include <cuda_bf16.h>

// ---------------- problem constants ----------------
#define NB    64          // batch
#define IMG   128         // input H=W
#define C1    64          // encoder mid channels
#define H1    64          // after stride-2 conv1
#define DQ    256         // code dim
#define H3    32          // latent H=W
#define KC    1024        // codebook size
#define NROWS (NB*H3*H3)  // 65536 latent vectors

// ---------------- scratch (device globals; no allocs allowed) ----------------
__device__ float g_z1[NB*C1*H1*H1];        // conv1 out, NCHW
__device__ float g_z2[NB*C1*H1*H1];        // conv2 out, NCHW
__device__ float g_z3[NROWS*DQ];           // conv3 out (z), NHWC rows
__device__ float g_e [NROWS*DQ];           // quantized e, NHWC rows
__device__ float g_d1[NB*64*64*64];        // deconv1 out, NHWC
__device__ float g_d2[NB*128*128*64];      // deconv2 out, NHWC
__device__ int   g_idx[NROWS];
__device__ float g_wnorm[KC];
__device__ float g_diff;

// ---------------- packed f32x2 helpers ----------------
typedef unsigned long long ull;
__device__ __forceinline__ void ffma2(ull& acc, ull a, ull b) {
    asm("fma.rn.f32x2 %0, %1, %2, %0;" : "+l"(acc) : "l"(a), "l"(b));
}
__device__ __forceinline__ ull pk2(float lo, float hi) {
    ull r; asm("mov.b64 %0, {%1, %2};" : "=l"(r) : "f"(lo), "f"(hi)); return r;
}
__device__ __forceinline__ float lo32(ull v) { return __uint_as_float((unsigned)(v & 0xFFFFFFFFull)); }
__device__ __forceinline__ float hi32(ull v) { return __uint_as_float((unsigned)(v >> 32)); }

// ================= conv1: 1->64, 5x5, s2, p2, ReLU =================
__global__ __launch_bounds__(256) void k_conv1(const float* __restrict__ x,
                                               const float* __restrict__ w,
                                               const float* __restrict__ bias) {
    __shared__ float s_in[35*35];
    __shared__ float s_w[64*25];
    const int b = blockIdx.z;
    const int X0 = blockIdx.x*16, Y0 = blockIdx.y*16;
    const int tid = threadIdx.y*16 + threadIdx.x;
    for (int i = tid; i < 1600; i += 256) s_w[i] = w[i];
    const int iy0 = 2*Y0 - 2, ix0 = 2*X0 - 2;
    const float* xb = x + b*IMG*IMG;
    for (int i = tid; i < 35*35; i += 256) {
        int r = i/35, c = i%35;
        int iy = iy0 + r, ix = ix0 + c;
        float v = 0.f;
        if (iy >= 0 && iy < IMG && ix >= 0 && ix < IMG) v = xb[iy*IMG + ix];
        s_in[i] = v;
    }
    __syncthreads();
    const int ty = threadIdx.y, tx = threadIdx.x;
    float in_reg[25];
#pragma unroll
    for (int ky = 0; ky < 5; ky++)
#pragma unroll
        for (int kx = 0; kx < 5; kx++)
            in_reg[ky*5+kx] = s_in[(2*ty+ky)*35 + 2*tx + kx];
    const int oy = Y0 + ty, ox = X0 + tx;
    float* outp = g_z1 + ((size_t)b*64*64*64) + oy*64 + ox;
#pragma unroll 4
    for (int oc = 0; oc < 64; oc++) {
        float s = bias[oc];
#pragma unroll
        for (int k = 0; k < 25; k++) s = fmaf(s_w[oc*25+k], in_reg[k], s);
        outp[(size_t)oc*4096] = fmaxf(s, 0.f);
    }
}

// ================= conv2 (f32x2): 64->64, 5x5, s1, p2, ReLU =================
__global__ __launch_bounds__(256) void k_conv2(const float* __restrict__ w,
                                               const float* __restrict__ bias) {
    __shared__ float2 s_in2[12*21];
    __shared__ float  s_w[64*25];
    const int b = blockIdx.z;
    const int X0 = blockIdx.x*32, Y0 = blockIdx.y*8;
    const int tid = threadIdx.x;
    const int ocg  = tid >> 5;
    const int slot = tid & 31;
    const int sy = slot >> 2, sx = slot & 3;

    ull acc[8][4];
#pragma unroll
    for (int j = 0; j < 8; j++)
#pragma unroll
        for (int kp = 0; kp < 4; kp++) acc[j][kp] = 0ull;

    for (int ic = 0; ic < 64; ic++) {
        const float* inp = g_z1 + ((size_t)(b*64 + ic))*4096;
        for (int i = tid; i < 240; i += 256) {
            int r = i/20, c = i%20;
            int iy = Y0 - 2 + r;
            int ix0 = X0 - 2 + c, ix1 = ix0 + 16;
            float v0 = 0.f, v1 = 0.f;
            if (iy >= 0 && iy < 64) {
                if (ix0 >= 0 && ix0 < 64) v0 = inp[iy*64 + ix0];
                if (ix1 >= 0 && ix1 < 64) v1 = inp[iy*64 + ix1];
            }
            s_in2[r*21 + c] = make_float2(v0, v1);
        }
        for (int i = tid; i < 1600; i += 256)
            s_w[i] = w[((i/25)*64 + ic)*25 + (i%25)];
        __syncthreads();

#pragma unroll
        for (int ky = 0; ky < 5; ky++) {
#pragma unroll
            for (int kx = 0; kx < 5; kx++) {
                const int tap = ky*5 + kx;
                ull wd[8];
#pragma unroll
                for (int j = 0; j < 8; j++) {
                    float wv = s_w[(ocg*8 + j)*25 + tap];
                    wd[j] = pk2(wv, wv);
                }
                ull ip[4];
#pragma unroll
                for (int kp = 0; kp < 4; kp++)
                    ip[kp] = *reinterpret_cast<const ull*>(&s_in2[(sy+ky)*21 + sx + 4*kp + kx]);
#pragma unroll
                for (int j = 0; j < 8; j++)
#pragma unroll
                    for (int kp = 0; kp < 4; kp++)
                        ffma2(acc[j][kp], ip[kp], wd[j]);
            }
        }
        __syncthreads();
    }
    const int oy = Y0 + sy;
#pragma unroll
    for (int j = 0; j < 8; j++) {
        const int oc = ocg*8 + j;
        const float bb = bias[oc];
        float* o = g_z2 + ((size_t)(b*64 + oc))*4096 + oy*64;
#pragma unroll
        for (int kp = 0; kp < 4; kp++) {
            int x0 = X0 + sx + 4*kp;
            o[x0]      = fmaxf(lo32(acc[j][kp]) + bb, 0.f);
            o[x0 + 16] = fmaxf(hi32(acc[j][kp]) + bb, 0.f);
        }
    }
}

// ================= conv3 (f32x2): 64->256, 5x5, s2, p2 (linear) -> NHWC z =================
__global__ __launch_bounds__(256) void k_conv3(const float* __restrict__ w,
                                               const float* __restrict__ bias) {
    __shared__ float2 s_in2[19*35];
    __shared__ float  s_w[64*25];
    const int bz = blockIdx.z;
    const int b = bz >> 2, ocb = bz & 3;
    const int Y0 = blockIdx.y*8;
    const int tid = threadIdx.x;
    const int ocg  = tid >> 5;
    const int slot = tid & 31;
    const int sy = slot >> 2, sx = slot & 3;

    ull acc[8][4];
#pragma unroll
    for (int j = 0; j < 8; j++)
#pragma unroll
        for (int kp = 0; kp < 4; kp++) acc[j][kp] = 0ull;

    const int iy0 = 2*Y0 - 2;
    for (int ic = 0; ic < 64; ic++) {
        const float* inp = g_z2 + ((size_t)(b*64 + ic))*4096;
        for (int i = tid; i < 665; i += 256) {
            int r = i/35, c = i%35;
            int iy = iy0 + r;
            int ix0 = c - 2, ix1 = c + 30;
            float v0 = 0.f, v1 = 0.f;
            if (iy >= 0 && iy < 64) {
                if (ix0 >= 0 && ix0 < 64) v0 = inp[iy*64 + ix0];
                if (ix1 < 64)             v1 = inp[iy*64 + ix1];
            }
            s_in2[r*35 + c] = make_float2(v0, v1);
        }
        for (int i = tid; i < 1600; i += 256) {
            int ocl = i/25, tap = i%25;
            s_w[i] = w[(((ocb*64 + ocl))*64 + ic)*25 + tap];
        }
        __syncthreads();

#pragma unroll
        for (int ky = 0; ky < 5; ky++) {
#pragma unroll
            for (int kx = 0; kx < 5; kx++) {
                const int tap = ky*5 + kx;
                ull wd[8];
#pragma unroll
                for (int j = 0; j < 8; j++) {
                    float wv = s_w[(ocg*8 + j)*25 + tap];
                    wd[j] = pk2(wv, wv);
                }
                ull ip[4];
#pragma unroll
                for (int kp = 0; kp < 4; kp++)
                    ip[kp] = *reinterpret_cast<const ull*>(&s_in2[(2*sy+ky)*35 + 2*sx + 8*kp + kx]);
#pragma unroll
                for (int j = 0; j < 8; j++)
#pragma unroll
                    for (int kp = 0; kp < 4; kp++)
                        ffma2(acc[j][kp], ip[kp], wd[j]);
            }
        }
        __syncthreads();
    }
    const int oy = Y0 + sy;
#pragma unroll
    for (int j = 0; j < 8; j++) {
        const int oc = ocb*64 + ocg*8 + j;
        const float bb = bias[oc];
#pragma unroll
        for (int kp = 0; kp < 4; kp++) {
            int x0 = sx + 4*kp;
            size_t base = ((size_t)(b*H3 + oy)*H3)*DQ;
            g_z3[base + (size_t)x0*DQ + oc]        = lo32(acc[j][kp]) + bb;
            g_z3[base + (size_t)(x0+16)*DQ + oc]   = hi32(acc[j][kp]) + bb;
        }
    }
}

// ================= codebook norms (+ zero g_diff for this replay) =================
__global__ void k_wnorm(const float* __restrict__ cb) {
    if (blockIdx.x == 0 && threadIdx.x == 0) g_diff = 0.f;
    int wid = (blockIdx.x*blockDim.x + threadIdx.x) >> 5;
    int lane = threadIdx.x & 31;
    if (wid >= KC) return;
    float s = 0.f;
    for (int d = lane; d < DQ; d += 32) { float v = cb[wid*DQ + d]; s = fmaf(v, v, s); }
#pragma unroll
    for (int off = 16; off > 0; off >>= 1) s += __shfl_xor_sync(0xFFFFFFFFu, s, off);
    if (lane == 0) g_wnorm[wid] = s;
}

// ================= quantize (f32x2) + fused gather/diff epilogue =================
__device__ __forceinline__ unsigned fkey(float f) {
    unsigned u = __float_as_uint(f);
    return (u & 0x80000000u) ? ~u : (u | 0x80000000u);
}
__global__ __launch_bounds__(256) void k_quant(const float* __restrict__ cb) {
    __shared__ float sA [64*65];       // [row][d]
    __shared__ float sBt[64*66];       // [d][code]  (transposed tile)
    __shared__ float s_wn[64];
    __shared__ unsigned long long s_best[64];
    __shared__ float red[256];
    const int tid = threadIdx.x;
    const int row0 = blockIdx.x*64;
    if (tid < 64) s_best[tid] = 0xFFFFFFFFFFFFFFFFULL;
    const int cg = tid & 15, rg = tid >> 4;

    for (int cc = 0; cc < 16; cc++) {
        __syncthreads();
        if (tid < 64) s_wn[tid] = g_wnorm[cc*64 + tid];
        ull acc2[4][2];
#pragma unroll
        for (int i = 0; i < 4; i++) { acc2[i][0] = 0ull; acc2[i][1] = 0ull; }

        for (int dc = 0; dc < 4; dc++) {
            for (int i = tid; i < 4096; i += 256) {
                int r = i >> 6, d = i & 63;
                sA[r*65 + d] = g_z3[(size_t)(row0 + r)*DQ + dc*64 + d];
            }
            for (int i = tid; i < 4096; i += 256) {
                int c = i >> 6, d = i & 63;
                sBt[d*66 + c] = cb[(size_t)(cc*64 + c)*DQ + dc*64 + d];
            }
            __syncthreads();
#pragma unroll 4
            for (int d = 0; d < 64; d++) {
                ull a2[4];
#pragma unroll
                for (int i = 0; i < 4; i++) {
                    float av = sA[(rg*4 + i)*65 + d];
                    a2[i] = pk2(av, av);
                }
                ull b0 = *reinterpret_cast<const ull*>(&sBt[d*66 + cg*4]);
                ull b1 = *reinterpret_cast<const ull*>(&sBt[d*66 + cg*4 + 2]);
#pragma unroll
                for (int i = 0; i < 4; i++) {
                    ffma2(acc2[i][0], a2[i], b0);
                    ffma2(acc2[i][1], a2[i], b1);
                }
            }
            __syncthreads();
        }
#pragma unroll
        for (int i = 0; i < 4; i++) {
            int r = rg*4 + i;
            float dot[4] = { lo32(acc2[i][0]), hi32(acc2[i][0]),
                             lo32(acc2[i][1]), hi32(acc2[i][1]) };
            unsigned long long best = 0xFFFFFFFFFFFFFFFFULL;
#pragma unroll
            for (int j = 0; j < 4; j++) {
                int c = cc*64 + cg*4 + j;
                float dist = s_wn[cg*4 + j] - 2.f*dot[j];
                unsigned long long p = ((unsigned long long)fkey(dist) << 32) | (unsigned)c;
                if (p < best) best = p;
            }
            atomicMin(&s_best[r], best);
        }
    }
    __syncthreads();
    if (tid < 64) g_idx[row0 + tid] = (int)(s_best[tid] & 0xFFFFFFFFULL);
    __syncthreads();

    // ---- fused gather + diff epilogue: thread tid = channel tid for 64 rows ----
    float local = 0.f;
    for (int r = 0; r < 64; r++) {
        int id = (int)(s_best[r] & 0xFFFFFFFFULL);
        float ev = cb[(size_t)id*DQ + tid];
        float zv = g_z3[(size_t)(row0 + r)*DQ + tid];
        g_e[(size_t)(row0 + r)*DQ + tid] = ev;
        float d = zv - ev;
        local = fmaf(d, d, local);
    }
    red[tid] = local;
    __syncthreads();
    for (int s = 128; s > 0; s >>= 1) {
        if (tid < s) red[tid] += red[tid + s];
        __syncthreads();
    }
    if (tid == 0) atomicAdd(&g_diff, red[0]);
}

__global__ void k_diff_final(float* __restrict__ out) {
    if (threadIdx.x == 0) out[0] = g_diff * (1.0f / 16777216.0f);
}

// ================= deconv (f32x2, double-buffered, R12 version) + ReLU =================
// Scalar s_in staging + pk2 in the hot loop (the R14 float2-prepack variant
// regressed ~+900us from smem bank conflicts; this is the proven-best form).
template<int STAGE>
__global__ __launch_bounds__(256) void k_deconv(const float* __restrict__ w,
                                                const float* __restrict__ bias) {
    constexpr int ICTOT = (STAGE == 1) ? 256 : 64;
    constexpr int INHW  = (STAGE == 1) ? 32  : 64;
    constexpr int OUTHW = (STAGE == 1) ? 64  : 128;
    constexpr int NICC  = ICTOT / 8;
    const float* __restrict__ in  = (STAGE == 1) ? g_e  : g_d1;
    float*       __restrict__ out = (STAGE == 1) ? g_d1 : g_d2;

    __shared__ float s_in[2][900];                    // 10x10 px x 8 ic, pitch 9
    __shared__ __align__(16) float s_w[2][8*16*34];   // [icl][tap][oc32] pitch 34
    const int b = blockIdx.z >> 1, ochalf = blockIdx.z & 1;
    const int X0 = blockIdx.x*16, Y0 = blockIdx.y*16;
    const int tid = threadIdx.x;
    const int ocgrp = tid >> 5;        // 0..7 -> 4 oc each
    const int slot = tid & 31;
    const int sy = slot >> 2, sx = slot & 3;
    ull acc2[2][4][2];                 // [dy][dx][oc-pair]
#pragma unroll
    for (int a = 0; a < 2; a++)
#pragma unroll
        for (int c = 0; c < 4; c++)
#pragma unroll
            for (int o = 0; o < 2; o++) acc2[a][c][o] = 0ull;

    const int iyb = (Y0 >> 1) - 1, ixb = (X0 >> 1) - 1;

    auto stage = [&](int icc, int buf) {
        for (int i = tid; i < 800; i += 256) {
            int icl = i & 7;
            int p = i >> 3;
            int c = p % 10, r = p / 10;
            int iy = iyb + r, ix = ixb + c;
            float v = 0.f;
            if (iy >= 0 && iy < INHW && ix >= 0 && ix < INHW)
                v = in[((size_t)(b*INHW + iy)*INHW + ix)*ICTOT + icc*8 + icl];
            s_in[buf][p*9 + icl] = v;
        }
        // COALESCED weight staging: linear gmem j -> smem scatter.
        for (int j = tid; j < 4096; j += 256) {
            int icl = j >> 9, rem = j & 511;
            int ocl = rem >> 4, tap = rem & 15;
            s_w[buf][(icl*16 + tap)*34 + ocl] =
                w[(size_t)icc*8192 + icl*1024 + ochalf*512 + rem];
        }
    };

    stage(0, 0);
    __syncthreads();

    for (int icc = 0; icc < NICC; icc++) {
        const int cur = icc & 1;
        if (icc + 1 < NICC) stage(icc + 1, cur ^ 1);

#pragma unroll
        for (int icl = 0; icl < 8; icl++) {
            ull rp[3][4];
#pragma unroll
            for (int a = 0; a < 3; a++)
#pragma unroll
                for (int c = 0; c < 4; c++) {
                    float v = s_in[cur][((sy + a)*10 + 2*sx + c)*9 + icl];
                    rp[a][c] = pk2(v, v);
                }
#pragma unroll
            for (int op = 0; op < 2; op++) {
                const int wofs = ocgrp*4 + op*2;
#pragma unroll
                for (int dy = 0; dy < 2; dy++) {
                    // 8 taps live for this dy: ky = (1-dy)+2a, kx = 0..3
                    ull w2[8];
#pragma unroll
                    for (int a = 0; a < 2; a++)
#pragma unroll
                        for (int kx = 0; kx < 4; kx++)
                            w2[a*4 + kx] = *reinterpret_cast<const ull*>(
                                &s_w[cur][(icl*16 + ((1 - dy) + 2*a)*4 + kx)*34 + wofs]);
#pragma unroll
                    for (int dx = 0; dx < 4; dx++) {
                        const int ib = 1 + ((dx + 1) >> 1);
#pragma unroll
                        for (int a = 0; a < 2; a++)
#pragma unroll
                            for (int c = 0; c < 2; c++) {
                                int kx = ((dx & 1) ? 0 : 1) + 2*c;
                                ffma2(acc2[dy][dx][op], rp[dy + 1 - a][ib - c], w2[a*4 + kx]);
                            }
                    }
                }
            }
        }
        __syncthreads();
    }
#pragma unroll
    for (int dy = 0; dy < 2; dy++)
#pragma unroll
        for (int dx = 0; dx < 4; dx++) {
            int py = Y0 + 2*sy + dy;
            int px = X0 + 4*sx + dx;
            float* o = out + ((size_t)(b*OUTHW + py)*OUTHW + px)*64 + ochalf*32;
#pragma unroll
            for (int op = 0; op < 2; op++) {
                int ocl = ocgrp*4 + op*2;
                int oc  = ochalf*32 + ocl;
                o[ocl]     = fmaxf(lo32(acc2[dy][dx][op]) + bias[oc],     0.f);
                o[ocl + 1] = fmaxf(hi32(acc2[dy][dx][op]) + bias[oc + 1], 0.f);
            }
        }
}

// ================= final conv 64->1, 3x3, s1, p1 + tanh =================
__global__ __launch_bounds__(256) void k_final(const float* __restrict__ w,
                                               const float* __restrict__ bias,
                                               float* __restrict__ out) {
    __shared__ float s_w[576];
    __shared__ float s_in[324*17 + 16];
    const int b = blockIdx.z;
    const int X0 = blockIdx.x*16, Y0 = blockIdx.y*16;
    const int tid = threadIdx.x;
    const int ty = tid >> 4, tx = tid & 15;
    for (int i = tid; i < 576; i += 256) s_w[i] = w[i];
    float acc = bias[0];
    for (int icc = 0; icc < 4; icc++) {
        __syncthreads();
        for (int i = tid; i < 324*16; i += 256) {
            int icl = i & 15;
            int p = i >> 4;
            int c = p % 18, r = p / 18;
            int iy = Y0 - 1 + r, ix = X0 - 1 + c;
            float v = 0.f;
            if (iy >= 0 && iy < 128 && ix >= 0 && ix < 128)
                v = g_d2[((size_t)(b*128 + iy)*128 + ix)*64 + icc*16 + icl];
            s_in[p*17 + icl] = v;
        }
        __syncthreads();
#pragma unroll 4
        for (int icl = 0; icl < 16; icl++) {
            int ic = icc*16 + icl;
#pragma unroll
            for (int ky = 0; ky < 3; ky++)
#pragma unroll
                for (int kx = 0; kx < 3; kx++)
                    acc = fmaf(s_w[ic*9 + ky*3 + kx],
                               s_in[((ty + ky)*18 + tx + kx)*17 + icl], acc);
        }
    }
    out[(size_t)b*16384 + (Y0 + ty)*128 + (X0 + tx)] = tanhf(acc);
}

// ================= launch =================
extern "C" void kernel_launch(void* const* d_in, const int* in_sizes, int n_in,
                              void* d_out, int out_size) {
    const float* ptr[14];
    {
        bool used[32];
        for (int i = 0; i < 32; i++) used[i] = false;
        auto find_nth = [&](int sz) -> const float* {
            for (int i = 0; i < n_in; i++) {
                if (!used[i] && in_sizes[i] == sz) { used[i] = true; return (const float*)d_in[i]; }
            }
            return (const float*)d_in[0];
        };
        ptr[0]  = find_nth(1048576);  // x
        ptr[1]  = find_nth(1600);     // enc_w1
        ptr[3]  = find_nth(102400);   // enc_w2
        ptr[5]  = find_nth(409600);   // enc_w3
        ptr[6]  = find_nth(256);      // enc_b3
        ptr[7]  = find_nth(262144);   // codebook (first occurrence)
        ptr[8]  = find_nth(262144);   // dec_w1  (second occurrence)
        ptr[10] = find_nth(65536);    // dec_w2
        ptr[12] = find_nth(576);      // dec_w3
        ptr[13] = find_nth(1);        // dec_b3
        ptr[2]  = find_nth(64);       // enc_b1 (all 64-vecs are zeros)
        ptr[4]  = find_nth(64);       // enc_b2
        ptr[9]  = find_nth(64);       // dec_b1
        ptr[11] = find_nth(64);       // dec_b2
    }
    float* out = (float*)d_out;

    k_conv1<<<dim3(4,4,NB), dim3(16,16)>>>(ptr[0], ptr[1], ptr[2]);
    k_conv2<<<dim3(2,8,NB), 256>>>(ptr[3], ptr[4]);
    k_conv3<<<dim3(1,4,NB*4), 256>>>(ptr[5], ptr[6]);
    k_wnorm<<<128, 256>>>(ptr[7]);
    k_quant<<<NROWS/64, 256>>>(ptr[7]);
    k_diff_final<<<1, 32>>>(out + (out_size - 1));
    k_deconv<1><<<dim3(4,4,NB*2), 256>>>(ptr[8], ptr[9]);
    k_deconv<2><<<dim3(8,8,NB*2), 256>>>(ptr[10], ptr[11]);
    k_final<<<dim3(8,8,NB), 256>>>(ptr[12], ptr[13], out);
}

// round 16
// speedup vs baseline: 1.1448x; 1.0066x over previous
#include <cuda_runtime.h>
#include <cuda_bf16.h>

// ---------------- problem constants ----------------
#define NB    64          // batch
#define IMG   128         // input H=W
#define C1    64          // encoder mid channels
#define H1    64          // after stride-2 conv1
#define DQ    256         // code dim
#define H3    32          // latent H=W
#define KC    1024        // codebook size
#define NROWS (NB*H3*H3)  // 65536 latent vectors

// ---------------- scratch (device globals; no allocs allowed) ----------------
__device__ float g_z1[NB*C1*H1*H1];        // conv1 out, NCHW
__device__ float g_z2[NB*C1*H1*H1];        // conv2 out, NCHW
__device__ float g_z3[NROWS*DQ];           // conv3 out (z), NHWC rows
__device__ float g_d1[NB*64*64*64];        // deconv1 out, NHWC
__device__ float g_d2[NB*128*128*64];      // deconv2 out, NHWC
__device__ int   g_idx[NROWS];
__device__ float g_wnorm[KC];
__device__ float g_diff;

// ---------------- packed f32x2 helpers ----------------
typedef unsigned long long ull;
__device__ __forceinline__ void ffma2(ull& acc, ull a, ull b) {
    asm("fma.rn.f32x2 %0, %1, %2, %0;" : "+l"(acc) : "l"(a), "l"(b));
}
__device__ __forceinline__ ull pk2(float lo, float hi) {
    ull r; asm("mov.b64 %0, {%1, %2};" : "=l"(r) : "f"(lo), "f"(hi)); return r;
}
__device__ __forceinline__ float lo32(ull v) { return __uint_as_float((unsigned)(v & 0xFFFFFFFFull)); }
__device__ __forceinline__ float hi32(ull v) { return __uint_as_float((unsigned)(v >> 32)); }

// ================= conv1: 1->64, 5x5, s2, p2, ReLU =================
__global__ __launch_bounds__(256) void k_conv1(const float* __restrict__ x,
                                               const float* __restrict__ w,
                                               const float* __restrict__ bias) {
    __shared__ float s_in[35*35];
    __shared__ float s_w[64*25];
    const int b = blockIdx.z;
    const int X0 = blockIdx.x*16, Y0 = blockIdx.y*16;
    const int tid = threadIdx.y*16 + threadIdx.x;
    for (int i = tid; i < 1600; i += 256) s_w[i] = w[i];
    const int iy0 = 2*Y0 - 2, ix0 = 2*X0 - 2;
    const float* xb = x + b*IMG*IMG;
    for (int i = tid; i < 35*35; i += 256) {
        int r = i/35, c = i%35;
        int iy = iy0 + r, ix = ix0 + c;
        float v = 0.f;
        if (iy >= 0 && iy < IMG && ix >= 0 && ix < IMG) v = xb[iy*IMG + ix];
        s_in[i] = v;
    }
    __syncthreads();
    const int ty = threadIdx.y, tx = threadIdx.x;
    float in_reg[25];
#pragma unroll
    for (int ky = 0; ky < 5; ky++)
#pragma unroll
        for (int kx = 0; kx < 5; kx++)
            in_reg[ky*5+kx] = s_in[(2*ty+ky)*35 + 2*tx + kx];
    const int oy = Y0 + ty, ox = X0 + tx;
    float* outp = g_z1 + ((size_t)b*64*64*64) + oy*64 + ox;
#pragma unroll 4
    for (int oc = 0; oc < 64; oc++) {
        float s = bias[oc];
#pragma unroll
        for (int k = 0; k < 25; k++) s = fmaf(s_w[oc*25+k], in_reg[k], s);
        outp[(size_t)oc*4096] = fmaxf(s, 0.f);
    }
}

// ================= conv2 (f32x2): 64->64, 5x5, s1, p2, ReLU =================
__global__ __launch_bounds__(256) void k_conv2(const float* __restrict__ w,
                                               const float* __restrict__ bias) {
    __shared__ float2 s_in2[12*21];
    __shared__ float  s_w[64*25];
    const int b = blockIdx.z;
    const int X0 = blockIdx.x*32, Y0 = blockIdx.y*8;
    const int tid = threadIdx.x;
    const int ocg  = tid >> 5;
    const int slot = tid & 31;
    const int sy = slot >> 2, sx = slot & 3;

    ull acc[8][4];
#pragma unroll
    for (int j = 0; j < 8; j++)
#pragma unroll
        for (int kp = 0; kp < 4; kp++) acc[j][kp] = 0ull;

    for (int ic = 0; ic < 64; ic++) {
        const float* inp = g_z1 + ((size_t)(b*64 + ic))*4096;
        for (int i = tid; i < 240; i += 256) {
            int r = i/20, c = i%20;
            int iy = Y0 - 2 + r;
            int ix0 = X0 - 2 + c, ix1 = ix0 + 16;
            float v0 = 0.f, v1 = 0.f;
            if (iy >= 0 && iy < 64) {
                if (ix0 >= 0 && ix0 < 64) v0 = inp[iy*64 + ix0];
                if (ix1 >= 0 && ix1 < 64) v1 = inp[iy*64 + ix1];
            }
            s_in2[r*21 + c] = make_float2(v0, v1);
        }
        for (int i = tid; i < 1600; i += 256)
            s_w[i] = w[((i/25)*64 + ic)*25 + (i%25)];
        __syncthreads();

#pragma unroll
        for (int ky = 0; ky < 5; ky++) {
#pragma unroll
            for (int kx = 0; kx < 5; kx++) {
                const int tap = ky*5 + kx;
                ull wd[8];
#pragma unroll
                for (int j = 0; j < 8; j++) {
                    float wv = s_w[(ocg*8 + j)*25 + tap];
                    wd[j] = pk2(wv, wv);
                }
                ull ip[4];
#pragma unroll
                for (int kp = 0; kp < 4; kp++)
                    ip[kp] = *reinterpret_cast<const ull*>(&s_in2[(sy+ky)*21 + sx + 4*kp + kx]);
#pragma unroll
                for (int j = 0; j < 8; j++)
#pragma unroll
                    for (int kp = 0; kp < 4; kp++)
                        ffma2(acc[j][kp], ip[kp], wd[j]);
            }
        }
        __syncthreads();
    }
    const int oy = Y0 + sy;
#pragma unroll
    for (int j = 0; j < 8; j++) {
        const int oc = ocg*8 + j;
        const float bb = bias[oc];
        float* o = g_z2 + ((size_t)(b*64 + oc))*4096 + oy*64;
#pragma unroll
        for (int kp = 0; kp < 4; kp++) {
            int x0 = X0 + sx + 4*kp;
            o[x0]      = fmaxf(lo32(acc[j][kp]) + bb, 0.f);
            o[x0 + 16] = fmaxf(hi32(acc[j][kp]) + bb, 0.f);
        }
    }
}

// ================= conv3 (f32x2): 64->256, 5x5, s2, p2 (linear) -> NHWC z =================
__global__ __launch_bounds__(256) void k_conv3(const float* __restrict__ w,
                                               const float* __restrict__ bias) {
    __shared__ float2 s_in2[19*35];
    __shared__ float  s_w[64*25];
    const int bz = blockIdx.z;
    const int b = bz >> 2, ocb = bz & 3;
    const int Y0 = blockIdx.y*8;
    const int tid = threadIdx.x;
    const int ocg  = tid >> 5;
    const int slot = tid & 31;
    const int sy = slot >> 2, sx = slot & 3;

    ull acc[8][4];
#pragma unroll
    for (int j = 0; j < 8; j++)
#pragma unroll
        for (int kp = 0; kp < 4; kp++) acc[j][kp] = 0ull;

    const int iy0 = 2*Y0 - 2;
    for (int ic = 0; ic < 64; ic++) {
        const float* inp = g_z2 + ((size_t)(b*64 + ic))*4096;
        for (int i = tid; i < 665; i += 256) {
            int r = i/35, c = i%35;
            int iy = iy0 + r;
            int ix0 = c - 2, ix1 = c + 30;
            float v0 = 0.f, v1 = 0.f;
            if (iy >= 0 && iy < 64) {
                if (ix0 >= 0 && ix0 < 64) v0 = inp[iy*64 + ix0];
                if (ix1 < 64)             v1 = inp[iy*64 + ix1];
            }
            s_in2[r*35 + c] = make_float2(v0, v1);
        }
        for (int i = tid; i < 1600; i += 256) {
            int ocl = i/25, tap = i%25;
            s_w[i] = w[(((ocb*64 + ocl))*64 + ic)*25 + tap];
        }
        __syncthreads();

#pragma unroll
        for (int ky = 0; ky < 5; ky++) {
#pragma unroll
            for (int kx = 0; kx < 5; kx++) {
                const int tap = ky*5 + kx;
                ull wd[8];
#pragma unroll
                for (int j = 0; j < 8; j++) {
                    float wv = s_w[(ocg*8 + j)*25 + tap];
                    wd[j] = pk2(wv, wv);
                }
                ull ip[4];
#pragma unroll
                for (int kp = 0; kp < 4; kp++)
                    ip[kp] = *reinterpret_cast<const ull*>(&s_in2[(2*sy+ky)*35 + 2*sx + 8*kp + kx]);
#pragma unroll
                for (int j = 0; j < 8; j++)
#pragma unroll
                    for (int kp = 0; kp < 4; kp++)
                        ffma2(acc[j][kp], ip[kp], wd[j]);
            }
        }
        __syncthreads();
    }
    const int oy = Y0 + sy;
#pragma unroll
    for (int j = 0; j < 8; j++) {
        const int oc = ocb*64 + ocg*8 + j;
        const float bb = bias[oc];
#pragma unroll
        for (int kp = 0; kp < 4; kp++) {
            int x0 = sx + 4*kp;
            size_t base = ((size_t)(b*H3 + oy)*H3)*DQ;
            g_z3[base + (size_t)x0*DQ + oc]        = lo32(acc[j][kp]) + bb;
            g_z3[base + (size_t)(x0+16)*DQ + oc]   = hi32(acc[j][kp]) + bb;
        }
    }
}

// ================= codebook norms (+ zero g_diff for this replay) =================
__global__ void k_wnorm(const float* __restrict__ cb) {
    if (blockIdx.x == 0 && threadIdx.x == 0) g_diff = 0.f;
    int wid = (blockIdx.x*blockDim.x + threadIdx.x) >> 5;
    int lane = threadIdx.x & 31;
    if (wid >= KC) return;
    float s = 0.f;
    for (int d = lane; d < DQ; d += 32) { float v = cb[wid*DQ + d]; s = fmaf(v, v, s); }
#pragma unroll
    for (int off = 16; off > 0; off >>= 1) s += __shfl_xor_sync(0xFFFFFFFFu, s, off);
    if (lane == 0) g_wnorm[wid] = s;
}

// ================= quantize (f32x2) + fused diff epilogue (no e store) =================
__device__ __forceinline__ unsigned fkey(float f) {
    unsigned u = __float_as_uint(f);
    return (u & 0x80000000u) ? ~u : (u | 0x80000000u);
}
__global__ __launch_bounds__(256) void k_quant(const float* __restrict__ cb) {
    __shared__ float sA [64*65];       // [row][d]
    __shared__ float sBt[64*66];       // [d][code]  (transposed tile)
    __shared__ float s_wn[64];
    __shared__ unsigned long long s_best[64];
    __shared__ float red[256];
    const int tid = threadIdx.x;
    const int row0 = blockIdx.x*64;
    if (tid < 64) s_best[tid] = 0xFFFFFFFFFFFFFFFFULL;
    const int cg = tid & 15, rg = tid >> 4;

    for (int cc = 0; cc < 16; cc++) {
        __syncthreads();
        if (tid < 64) s_wn[tid] = g_wnorm[cc*64 + tid];
        ull acc2[4][2];
#pragma unroll
        for (int i = 0; i < 4; i++) { acc2[i][0] = 0ull; acc2[i][1] = 0ull; }

        for (int dc = 0; dc < 4; dc++) {
            for (int i = tid; i < 4096; i += 256) {
                int r = i >> 6, d = i & 63;
                sA[r*65 + d] = g_z3[(size_t)(row0 + r)*DQ + dc*64 + d];
            }
            for (int i = tid; i < 4096; i += 256) {
                int c = i >> 6, d = i & 63;
                sBt[d*66 + c] = cb[(size_t)(cc*64 + c)*DQ + dc*64 + d];
            }
            __syncthreads();
#pragma unroll 4
            for (int d = 0; d < 64; d++) {
                ull a2[4];
#pragma unroll
                for (int i = 0; i < 4; i++) {
                    float av = sA[(rg*4 + i)*65 + d];
                    a2[i] = pk2(av, av);
                }
                ull b0 = *reinterpret_cast<const ull*>(&sBt[d*66 + cg*4]);
                ull b1 = *reinterpret_cast<const ull*>(&sBt[d*66 + cg*4 + 2]);
#pragma unroll
                for (int i = 0; i < 4; i++) {
                    ffma2(acc2[i][0], a2[i], b0);
                    ffma2(acc2[i][1], a2[i], b1);
                }
            }
            __syncthreads();
        }
#pragma unroll
        for (int i = 0; i < 4; i++) {
            int r = rg*4 + i;
            float dot[4] = { lo32(acc2[i][0]), hi32(acc2[i][0]),
                             lo32(acc2[i][1]), hi32(acc2[i][1]) };
            unsigned long long best = 0xFFFFFFFFFFFFFFFFULL;
#pragma unroll
            for (int j = 0; j < 4; j++) {
                int c = cc*64 + cg*4 + j;
                float dist = s_wn[cg*4 + j] - 2.f*dot[j];
                unsigned long long p = ((unsigned long long)fkey(dist) << 32) | (unsigned)c;
                if (p < best) best = p;
            }
            atomicMin(&s_best[r], best);
        }
    }
    __syncthreads();
    if (tid < 64) g_idx[row0 + tid] = (int)(s_best[tid] & 0xFFFFFFFFULL);
    __syncthreads();

    // ---- fused diff epilogue (no g_e store; deconv1 gathers cb directly) ----
    float local = 0.f;
    for (int r = 0; r < 64; r++) {
        int id = (int)(s_best[r] & 0xFFFFFFFFULL);
        float ev = cb[(size_t)id*DQ + tid];
        float zv = g_z3[(size_t)(row0 + r)*DQ + tid];
        float d = zv - ev;
        local = fmaf(d, d, local);
    }
    red[tid] = local;
    __syncthreads();
    for (int s = 128; s > 0; s >>= 1) {
        if (tid < s) red[tid] += red[tid + s];
        __syncthreads();
    }
    if (tid == 0) atomicAdd(&g_diff, red[0]);
}

__global__ void k_diff_final(float* __restrict__ out) {
    if (threadIdx.x == 0) out[0] = g_diff * (1.0f / 16777216.0f);
}

// ================= deconv (f32x2, double-buffered) + ReLU =================
// STAGE==1 gathers its input e on the fly: id = g_idx[pixel], v = cb[id*DQ+ch]
// (cb is 1MB -> L2-resident). Values identical to the old g_e path -> bit-exact.
template<int STAGE>
__global__ __launch_bounds__(256) void k_deconv(const float* __restrict__ w,
                                                const float* __restrict__ bias,
                                                const float* __restrict__ cbk) {
    constexpr int ICTOT = (STAGE == 1) ? 256 : 64;
    constexpr int INHW  = (STAGE == 1) ? 32  : 64;
    constexpr int OUTHW = (STAGE == 1) ? 64  : 128;
    constexpr int NICC  = ICTOT / 8;
    float* __restrict__ out = (STAGE == 1) ? g_d1 : g_d2;

    __shared__ float s_in[2][900];                    // 10x10 px x 8 ic, pitch 9
    __shared__ __align__(16) float s_w[2][8*16*34];   // [icl][tap][oc32] pitch 34
    const int b = blockIdx.z >> 1, ochalf = blockIdx.z & 1;
    const int X0 = blockIdx.x*16, Y0 = blockIdx.y*16;
    const int tid = threadIdx.x;
    const int ocgrp = tid >> 5;        // 0..7 -> 4 oc each
    const int slot = tid & 31;
    const int sy = slot >> 2, sx = slot & 3;
    ull acc2[2][4][2];                 // [dy][dx][oc-pair]
#pragma unroll
    for (int a = 0; a < 2; a++)
#pragma unroll
        for (int c = 0; c < 4; c++)
#pragma unroll
            for (int o = 0; o < 2; o++) acc2[a][c][o] = 0ull;

    const int iyb = (Y0 >> 1) - 1, ixb = (X0 >> 1) - 1;

    auto stage = [&](int icc, int buf) {
        for (int i = tid; i < 800; i += 256) {
            int icl = i & 7;
            int p = i >> 3;
            int c = p % 10, r = p / 10;
            int iy = iyb + r, ix = ixb + c;
            float v = 0.f;
            if (iy >= 0 && iy < INHW && ix >= 0 && ix < INHW) {
                if (STAGE == 1) {
                    int id = g_idx[b*(H3*H3) + iy*H3 + ix];
                    v = cbk[(size_t)id*DQ + icc*8 + icl];
                } else {
                    v = g_d1[((size_t)(b*INHW + iy)*INHW + ix)*ICTOT + icc*8 + icl];
                }
            }
            s_in[buf][p*9 + icl] = v;
        }
        // COALESCED weight staging: linear gmem j -> smem scatter.
        for (int j = tid; j < 4096; j += 256) {
            int icl = j >> 9, rem = j & 511;
            int ocl = rem >> 4, tap = rem & 15;
            s_w[buf][(icl*16 + tap)*34 + ocl] =
                w[(size_t)icc*8192 + icl*1024 + ochalf*512 + rem];
        }
    };

    stage(0, 0);
    __syncthreads();

    for (int icc = 0; icc < NICC; icc++) {
        const int cur = icc & 1;
        if (icc + 1 < NICC) stage(icc + 1, cur ^ 1);

#pragma unroll
        for (int icl = 0; icl < 8; icl++) {
            ull rp[3][4];
#pragma unroll
            for (int a = 0; a < 3; a++)
#pragma unroll
                for (int c = 0; c < 4; c++) {
                    float v = s_in[cur][((sy + a)*10 + 2*sx + c)*9 + icl];
                    rp[a][c] = pk2(v, v);
                }
#pragma unroll
            for (int op = 0; op < 2; op++) {
                const int wofs = ocgrp*4 + op*2;
#pragma unroll
                for (int dy = 0; dy < 2; dy++) {
                    // 8 taps live for this dy: ky = (1-dy)+2a, kx = 0..3
                    ull w2[8];
#pragma unroll
                    for (int a = 0; a < 2; a++)
#pragma unroll
                        for (int kx = 0; kx < 4; kx++)
                            w2[a*4 + kx] = *reinterpret_cast<const ull*>(
                                &s_w[cur][(icl*16 + ((1 - dy) + 2*a)*4 + kx)*34 + wofs]);
#pragma unroll
                    for (int dx = 0; dx < 4; dx++) {
                        const int ib = 1 + ((dx + 1) >> 1);
#pragma unroll
                        for (int a = 0; a < 2; a++)
#pragma unroll
                            for (int c = 0; c < 2; c++) {
                                int kx = ((dx & 1) ? 0 : 1) + 2*c;
                                ffma2(acc2[dy][dx][op], rp[dy + 1 - a][ib - c], w2[a*4 + kx]);
                            }
                    }
                }
            }
        }
        __syncthreads();
    }
#pragma unroll
    for (int dy = 0; dy < 2; dy++)
#pragma unroll
        for (int dx = 0; dx < 4; dx++) {
            int py = Y0 + 2*sy + dy;
            int px = X0 + 4*sx + dx;
            float* o = out + ((size_t)(b*OUTHW + py)*OUTHW + px)*64 + ochalf*32;
#pragma unroll
            for (int op = 0; op < 2; op++) {
                int ocl = ocgrp*4 + op*2;
                int oc  = ochalf*32 + ocl;
                o[ocl]     = fmaxf(lo32(acc2[dy][dx][op]) + bias[oc],     0.f);
                o[ocl + 1] = fmaxf(hi32(acc2[dy][dx][op]) + bias[oc + 1], 0.f);
            }
        }
}

// ================= final conv 64->1, 3x3, s1, p1 + tanh =================
__global__ __launch_bounds__(256) void k_final(const float* __restrict__ w,
                                               const float* __restrict__ bias,
                                               float* __restrict__ out) {
    __shared__ float s_w[576];
    __shared__ float s_in[324*17 + 16];
    const int b = blockIdx.z;
    const int X0 = blockIdx.x*16, Y0 = blockIdx.y*16;
    const int tid = threadIdx.x;
    const int ty = tid >> 4, tx = tid & 15;
    for (int i = tid; i < 576; i += 256) s_w[i] = w[i];
    float acc = bias[0];
    for (int icc = 0; icc < 4; icc++) {
        __syncthreads();
        for (int i = tid; i < 324*16; i += 256) {
            int icl = i & 15;
            int p = i >> 4;
            int c = p % 18, r = p / 18;
            int iy = Y0 - 1 + r, ix = X0 - 1 + c;
            float v = 0.f;
            if (iy >= 0 && iy < 128 && ix >= 0 && ix < 128)
                v = g_d2[((size_t)(b*128 + iy)*128 + ix)*64 + icc*16 + icl];
            s_in[p*17 + icl] = v;
        }
        __syncthreads();
#pragma unroll 4
        for (int icl = 0; icl < 16; icl++) {
            int ic = icc*16 + icl;
#pragma unroll
            for (int ky = 0; ky < 3; ky++)
#pragma unroll
                for (int kx = 0; kx < 3; kx++)
                    acc = fmaf(s_w[ic*9 + ky*3 + kx],
                               s_in[((ty + ky)*18 + tx + kx)*17 + icl], acc);
        }
    }
    out[(size_t)b*16384 + (Y0 + ty)*128 + (X0 + tx)] = tanhf(acc);
}

// ================= launch =================
extern "C" void kernel_launch(void* const* d_in, const int* in_sizes, int n_in,
                              void* d_out, int out_size) {
    const float* ptr[14];
    {
        bool used[32];
        for (int i = 0; i < 32; i++) used[i] = false;
        auto find_nth = [&](int sz) -> const float* {
            for (int i = 0; i < n_in; i++) {
                if (!used[i] && in_sizes[i] == sz) { used[i] = true; return (const float*)d_in[i]; }
            }
            return (const float*)d_in[0];
        };
        ptr[0]  = find_nth(1048576);  // x
        ptr[1]  = find_nth(1600);     // enc_w1
        ptr[3]  = find_nth(102400);   // enc_w2
        ptr[5]  = find_nth(409600);   // enc_w3
        ptr[6]  = find_nth(256);      // enc_b3
        ptr[7]  = find_nth(262144);   // codebook (first occurrence)
        ptr[8]  = find_nth(262144);   // dec_w1  (second occurrence)
        ptr[10] = find_nth(65536);    // dec_w2
        ptr[12] = find_nth(576);      // dec_w3
        ptr[13] = find_nth(1);        // dec_b3
        ptr[2]  = find_nth(64);       // enc_b1 (all 64-vecs are zeros)
        ptr[4]  = find_nth(64);       // enc_b2
        ptr[9]  = find_nth(64);       // dec_b1
        ptr[11] = find_nth(64);       // dec_b2
    }
    float* out = (float*)d_out;

    k_conv1<<<dim3(4,4,NB), dim3(16,16)>>>(ptr[0], ptr[1], ptr[2]);
    k_conv2<<<dim3(2,8,NB), 256>>>(ptr[3], ptr[4]);
    k_conv3<<<dim3(1,4,NB*4), 256>>>(ptr[5], ptr[6]);
    k_wnorm<<<128, 256>>>(ptr[7]);
    k_quant<<<NROWS/64, 256>>>(ptr[7]);
    k_diff_final<<<1, 32>>>(out + (out_size - 1));
    k_deconv<1><<<dim3(4,4,NB*2), 256>>>(ptr[8], ptr[9], ptr[7]);
    k_deconv<2><<<dim3(8,8,NB*2), 256>>>(ptr[10], ptr[11], ptr[7]);
    k_final<<<dim3(8,8,NB), 256>>>(ptr[12], ptr[13], out);
}